// round 14
// baseline (speedup 1.0000x reference)
#include <cuda_runtime.h>

#define TT 512
#define BB 256
#define DD 256
#define HH 256
#define DH 512
#define TB (TT*BB)

typedef unsigned long long ull;

// scratch (allocation-free rule: static __device__ arrays)
// g_trig4[(t*6 + p)*256 + h] = (cosLo, cosHi, sinLo, sinHi) for PAIR p of row (t,h)
// pairs: p0=(f1,i1) p1=(f2,i2) p2=(f3,i3) p3=(g1,o1) p4=(g2,o2) p5=(g3,o3)
__device__ float4 g_trig4[TT * 6 * 256];
__device__ __align__(16) float g_hseq[TT * HH];   // hvec per step
__device__ __align__(16) float g_cvec[HH];        // final cell state

// named producer/consumer barriers (384 = full CTA count each phase)
#define BAR_ARV(id)  asm volatile("bar.arrive %0, %1;" :: "r"(id), "r"(384) : "memory")
#define BAR_WAIT(id) asm volatile("bar.sync %0, %1;"   :: "r"(id), "r"(384) : "memory")

// HW tanh (MUFU.TANH): 1 instruction, rel err ~2^-11.
__device__ __forceinline__ float tanh_hw(float x) {
    float r;
    asm("tanh.approx.f32 %0, %1;" : "=f"(r) : "f"(x));
    return r;
}

// packed f32x2 ops (FFMA2/FMUL2 — PTX-only, ptxas never auto-fuses)
__device__ __forceinline__ ull mul2(ull a, ull b) {
    ull r; asm("mul.rn.f32x2 %0, %1, %2;" : "=l"(r) : "l"(a), "l"(b)); return r;
}
__device__ __forceinline__ ull fma2(ull a, ull b, ull c) {
    ull r; asm("fma.rn.f32x2 %0, %1, %2, %3;" : "=l"(r) : "l"(a), "l"(b), "l"(c)); return r;
}
__device__ __forceinline__ void unpack2(ull v, float& lo, float& hi) {
    asm("mov.b64 {%0, %1}, %2;" : "=f"(lo), "=f"(hi) : "l"(v));
}

__constant__ ull HALF_HALF = 0x3F0000003F000000ULL;  // (0.5f, 0.5f)
__constant__ ull ONE_HALF  = 0x3F0000003F800000ULL;  // (1.0f lo, 0.5f hi)

// ---------------------------------------------------------------------------
// Kernel A: xp trig with PAIRED slot order.
// slot s (0..11): p=s>>1, h=s&1; p<3: W = h?Wi:Wf, wire q=p+1;
//                               p>=3: W = h?Wo:Wu, wire q=p-2.
// Tree reduce leaves slot s on lane via s = (b1)? 8+2b3+b4 : b4+2b3+4b2;
// pair partner (s^1) sits at lane^16. Writer stores (cLo,cHi,sLo,sHi).
// ---------------------------------------------------------------------------
__global__ __launch_bounds__(128, 3) void precompute_kernel(
    const float* __restrict__ x,
    const float* __restrict__ Wf, const float* __restrict__ bf, const float* __restrict__ pf,
    const float* __restrict__ Wi, const float* __restrict__ bi, const float* __restrict__ pi,
    const float* __restrict__ Wu, const float* __restrict__ bu, const float* __restrict__ pu,
    const float* __restrict__ Wo, const float* __restrict__ bo, const float* __restrict__ po)
{
    int tid = threadIdx.x;
    int lane = tid & 31;
    int gwarp = (blockIdx.x * 128 + tid) >> 5;
    int nwarp = (gridDim.x * 128) >> 5;
    const unsigned FULL = 0xffffffffu;

    float4 wa[12], wb[12];
#pragma unroll
    for (int j = 0; j < 12; ++j) {
        int p = j >> 1, h = j & 1;
        const float* Ws = (p < 3) ? (h ? Wi : Wf) : (h ? Wo : Wu);
        int q = (p < 3) ? (p + 1) : (p - 2);
        const float4* r4 = (const float4*)(Ws + q * DH);
        wa[j] = r4[lane];
        wb[j] = r4[32 + lane];
    }

    int b4 = (lane >> 4) & 1, b3 = (lane >> 3) & 1, b2 = (lane >> 2) & 1;
    int myj = (lane & 2) ? (8 + b4 + 2 * b3) : (b4 + 2 * b3 + 4 * b2);
    float off;
    {
        int p = myj >> 1, h = myj & 1;
        const float* bs = (p < 3) ? (h ? bi : bf) : (h ? bo : bu);
        const float* ps = (p < 3) ? (h ? pi : pf) : (h ? po : pu);
        int q = (p < 3) ? (p + 1) : (p - 2);
        off = bs[q] + ps[q];
    }
    bool writer = ((lane & 0x13) == 0) || ((lane & 0x17) == 2);
    int plane = myj >> 1;

    const float4* x4 = (const float4*)x;

    int row = gwarp;
    if (row >= TB) return;
    // software pipeline, prefetch distance 3
    float4 x0a = x4[row * 64 + lane];
    float4 x0b = x4[row * 64 + 32 + lane];
    float4 x1a = make_float4(0.f,0.f,0.f,0.f), x1b = x1a, x2a = x1a, x2b = x1a;
    if (row + nwarp < TB) {
        x1a = x4[(row + nwarp) * 64 + lane];
        x1b = x4[(row + nwarp) * 64 + 32 + lane];
    }
    if (row + 2 * nwarp < TB) {
        x2a = x4[(row + 2 * nwarp) * 64 + lane];
        x2b = x4[(row + 2 * nwarp) * 64 + 32 + lane];
    }

#pragma unroll 3
    for (; row < TB; row += nwarp) {
        int frow = row + 3 * nwarp;
        float4 fa, fb;
        if (frow < TB) {
            fa = x4[frow * 64 + lane];
            fb = x4[frow * 64 + 32 + lane];
        }

        float v[12];
#pragma unroll
        for (int j = 0; j < 12; ++j) {
            v[j] = x0a.x * wa[j].x + x0a.y * wa[j].y + x0a.z * wa[j].z + x0a.w * wa[j].w
                 + x0b.x * wb[j].x + x0b.y * wb[j].y + x0b.z * wb[j].z + x0b.w * wb[j].w;
        }

        // tree-combined multi-reduce: 12 sums in 24 shfls
#pragma unroll
        for (int j = 0; j < 12; ++j)
            v[j] += __shfl_xor_sync(FULL, v[j], 16);
        float w[6];
#pragma unroll
        for (int k = 0; k < 6; ++k) {
            w[k] = (lane & 16) ? v[2 * k + 1] : v[2 * k];
            w[k] += __shfl_xor_sync(FULL, w[k], 8);
        }
        float y[3];
#pragma unroll
        for (int m = 0; m < 3; ++m) {
            y[m] = (lane & 8) ? w[2 * m + 1] : w[2 * m];
            y[m] += __shfl_xor_sync(FULL, y[m], 4);
        }
        float z0 = (lane & 4) ? y[1] : y[0];
        float z1 = y[2];
        z0 += __shfl_xor_sync(FULL, z0, 2);
        z1 += __shfl_xor_sync(FULL, z1, 2);
        float u = (lane & 2) ? z1 : z0;
        u += __shfl_xor_sync(FULL, u, 1);

        float th = u + off;
        float s, c;
        __sincosf(th, &s, &c);
        float c1 = __shfl_xor_sync(FULL, c, 16);
        float s1 = __shfl_xor_sync(FULL, s, 16);
        if (writer) {
            int t = row >> 8, h = row & 255;
            g_trig4[(t * 6 + plane) * 256 + h] = make_float4(c, c1, s, s1);
        }

        x0a = x1a; x0b = x1b;
        x1a = x2a; x1b = x2b;
        x2a = fa;  x2b = fb;
    }
}

// ---------------------------------------------------------------------------
// Kernel B: warp-specialized recurrence, PACKED-f32x2 gate phase.
// FMA-pipe throughput bound (2/cyc/SM) -> halve gate FMA ops via FFMA2/FMUL2.
//   gate warps 0-7  (256 thr): per-h gate math, cv in register
//   reduce warps 8-11: warp rw owns gate rw; stores cos and NEGATED sin into
//     paired layout chs2/shs2 (pair p = plane, half = f/i or g/o).
// ---------------------------------------------------------------------------
__device__ __forceinline__ void gate_half(
    int t, int pf_t, int tid,
    ull* vc, ull* vs,               // [6] packed (cLo,cHi), (sLo,sHi)
    float& cvr, float* hv_sm, float* chs2, float* shs2)
{
    // packed cs pairs: C[p] = (cos_lo, cos_hi), Sn[p] = (-sin_lo, -sin_hi)
    ulonglong2 Cq0 = *(const ulonglong2*)(chs2 + 0);
    ulonglong2 Cq1 = *(const ulonglong2*)(chs2 + 4);
    ulonglong2 Cq2 = *(const ulonglong2*)(chs2 + 8);
    ulonglong2 Sq0 = *(const ulonglong2*)(shs2 + 0);
    ulonglong2 Sq1 = *(const ulonglong2*)(shs2 + 4);
    ulonglong2 Sq2 = *(const ulonglong2*)(shs2 + 8);

    // r[p] = cos(xp)*C + sin(xp)*(-S), two wires per op
    ull r0 = fma2(vs[0], Sq0.x, mul2(vc[0], Cq0.x));
    ull r1 = fma2(vs[1], Sq0.y, mul2(vc[1], Cq0.y));
    ull r2 = fma2(vs[2], Sq1.x, mul2(vc[2], Cq1.x));
    ull r3 = fma2(vs[3], Sq1.y, mul2(vc[3], Cq1.y));
    ull r4 = fma2(vs[4], Sq2.x, mul2(vc[4], Cq2.x));
    ull r5 = fma2(vs[5], Sq2.y, mul2(vc[5], Cq2.y));

    // products: (f_arg, i_arg) and (g_arg, o_arg)
    ull AB = mul2(mul2(r0, r1), r2);
    ull CD = mul2(mul2(r3, r4), r5);
    AB = mul2(AB, HALF_HALF);   // halve both (sigmoid args)
    CD = mul2(CD, ONE_HALF);    // g unscaled, o halved

    float a, b, c, d;
    unpack2(AB, a, b);
    unpack2(CD, c, d);
    float f  = __fmaf_rn(0.5f, tanh_hw(a), 0.5f);
    float i  = __fmaf_rn(0.5f, tanh_hw(b), 0.5f);
    float g  = tanh_hw(c);
    float o  = __fmaf_rn(0.5f, tanh_hw(d), 0.5f);

    cvr = __fmaf_rn(f, cvr, i * g);
    float hx = o * tanh_hw(cvr);
    hv_sm[tid] = hx;
    BAR_ARV(1);                     // hv ready

    g_hseq[t * 256 + tid] = hx;     // off-chain
    if (pf_t < TT) {                // prefetch distance 2, pair-aligned LDG.64
        const ull* tp = (const ull*)g_trig4 + (size_t)pf_t * 3072 + 2 * tid;
#pragma unroll
        for (int p = 0; p < 6; ++p) {
            vc[p] = tp[512 * p];
            vs[p] = tp[512 * p + 1];
        }
    }
    BAR_WAIT(2);                    // cs(t) ready for next half-step
}

// pairwise-tree 8-element dot
__device__ __forceinline__ float dot8(float4 wa, float4 wb, float4 ha, float4 hb)
{
    float m0 = __fmaf_rn(wa.y, ha.y, wa.x * ha.x);
    float m1 = __fmaf_rn(wa.w, ha.w, wa.z * ha.z);
    float m2 = __fmaf_rn(wb.y, hb.y, wb.x * hb.x);
    float m3 = __fmaf_rn(wb.w, hb.w, wb.z * hb.z);
    return (m0 + m1) + (m2 + m3);
}

__global__ __launch_bounds__(384, 1) void recurrence_kernel(
    const float* __restrict__ Wf, const float* __restrict__ Wi,
    const float* __restrict__ Wu, const float* __restrict__ Wo)
{
    __shared__ __align__(16) float hv_sm[256];
    __shared__ __align__(16) float chs2[12];   // cos, paired layout
    __shared__ __align__(16) float shs2[12];   // NEGATED sin, paired layout

    int tid = threadIdx.x;
    int lane = tid & 31, warp = tid >> 5;

    if (tid < 12) { chs2[tid] = 1.0f; shs2[tid] = 0.0f; }  // hvec0=0 -> hdot=0
    __syncthreads();

    if (warp < 8) {
        // ---------------- gate role ----------------
        float cvr = 0.0f;
        ull Avc[6], Avs[6], Bvc[6], Bvs[6];
        {
            const ull* tp0 = (const ull*)g_trig4 + 2 * tid;
            const ull* tp1 = (const ull*)g_trig4 + 3072 + 2 * tid;
#pragma unroll
            for (int p = 0; p < 6; ++p) {
                Avc[p] = tp0[512 * p]; Avs[p] = tp0[512 * p + 1];
                Bvc[p] = tp1[512 * p]; Bvs[p] = tp1[512 * p + 1];
            }
        }
        for (int t = 0; t < TT; t += 2) {
            gate_half(t,     t + 2, tid, Avc, Avs, cvr, hv_sm, chs2, shs2);
            gate_half(t + 1, t + 3, tid, Bvc, Bvs, cvr, hv_sm, chs2, shs2);
        }
        g_cvec[tid] = cvr;
    } else {
        // ---------------- reduce role ----------------
        int rw = warp - 8;   // 0..3 -> f, i, g(u), o ; wires 1-3
        const float* Wsel = (rw == 0) ? Wf : (rw == 1) ? Wi : (rw == 2) ? Wu : Wo;
        float4 wa[3], wb[3];
#pragma unroll
        for (int k = 0; k < 3; ++k) {
            const float4* Wr4 = (const float4*)(Wsel + (1 + k) * DH + DD);
            wa[k] = Wr4[lane];
            wb[k] = Wr4[32 + lane];
        }
        const float4* hv4 = (const float4*)hv_sm;
        // lanes 0..5: kk = wire-1 = lane>>1; odd lane = (negated) sin
        int kk = lane >> 1;
        float* dst = (lane & 1) ? shs2 : chs2;
        // paired layout index: plane p = kk + 3*(rw>>1), half = rw&1
        int jj = 2 * (kk + 3 * (rw >> 1)) + (rw & 1);

        for (int t = 0; t < TT; ++t) {
            BAR_WAIT(1);            // hv ready
            float4 ha = hv4[lane];
            float4 hb = hv4[32 + lane];
            float s0 = dot8(wa[0], wb[0], ha, hb);
            float s1 = dot8(wa[1], wb[1], ha, hb);
            float s2 = dot8(wa[2], wb[2], ha, hb);
#pragma unroll
            for (int off = 16; off > 0; off >>= 1) {
                s0 += __shfl_xor_sync(0xffffffffu, s0, off);
                s1 += __shfl_xor_sync(0xffffffffu, s1, off);
                s2 += __shfl_xor_sync(0xffffffffu, s2, off);
            }
            if (lane < 6) {
                float sv = (kk == 0) ? s0 : (kk == 1) ? s1 : s2;
                float r = (lane & 1) ? -__sinf(sv) : __cosf(sv);
                dst[jj] = r;
            }
            BAR_ARV(2);             // cs ready
        }
    }
}

// ---------------------------------------------------------------------------
// Kernel C: broadcast outputs. out = [outs (T,B,H) | hx (B,H) | cx (B,H)],
// every b-row identical. Pure write bandwidth, float4.
// ---------------------------------------------------------------------------
__global__ void writeout_kernel(float4* __restrict__ out4)
{
    const int OUTS4 = TT * BB * (HH / 4);   // 8388608
    const int BH4 = BB * (HH / 4);          // 16384
    int i4 = blockIdx.x * blockDim.x + threadIdx.x;
    const float4* hs4 = (const float4*)g_hseq;
    const float4* cv4 = (const float4*)g_cvec;
    if (i4 < OUTS4) {
        int t = i4 >> 14;          // / (B*H/4)
        int h4 = i4 & 63;
        out4[i4] = hs4[t * 64 + h4];
    } else if (i4 < OUTS4 + BH4) {
        int h4 = i4 & 63;
        out4[i4] = hs4[(TT - 1) * 64 + h4];
    } else if (i4 < OUTS4 + 2 * BH4) {
        int h4 = i4 & 63;
        out4[i4] = cv4[h4];
    }
}

extern "C" void kernel_launch(void* const* d_in, const int* in_sizes, int n_in,
                              void* d_out, int out_size)
{
    const float* x  = (const float*)d_in[0];
    const float* Wf = (const float*)d_in[1];
    const float* bf = (const float*)d_in[2];
    const float* pf = (const float*)d_in[3];
    const float* Wi = (const float*)d_in[4];
    const float* bi = (const float*)d_in[5];
    const float* pi = (const float*)d_in[6];
    const float* Wu = (const float*)d_in[7];
    const float* bu = (const float*)d_in[8];
    const float* pu = (const float*)d_in[9];
    const float* Wo = (const float*)d_in[10];
    const float* bo = (const float*)d_in[11];
    const float* po = (const float*)d_in[12];

    precompute_kernel<<<444, 128>>>(x, Wf, bf, pf, Wi, bi, pi,
                                       Wu, bu, pu, Wo, bo, po);
    recurrence_kernel<<<1, 384>>>(Wf, Wi, Wu, Wo);

    const int total4 = (TT * BB * HH + 2 * BB * HH) / 4;   // 8421376
    writeout_kernel<<<(total4 + 255) / 256, 256>>>((float4*)d_out);
}

// round 15
// speedup vs baseline: 1.0069x; 1.0069x over previous
#include <cuda_runtime.h>

#define TT 512
#define BB 256
#define DD 256
#define HH 256
#define DH 512
#define TB (TT*BB)

typedef unsigned long long ull;

// scratch (allocation-free rule: static __device__ arrays)
// g_trig4[(t*6 + p)*256 + h] = (cosLo, cosHi, sinLo, sinHi) for PAIR p of row (t,h)
// pairs: p0=(f1,i1) p1=(f2,i2) p2=(f3,i3) p3=(g1,o1) p4=(g2,o2) p5=(g3,o3)
__device__ float4 g_trig4[TT * 6 * 256];
__device__ __align__(16) float g_hseq[TT * HH];   // hvec per step
__device__ __align__(16) float g_cvec[HH];        // final cell state

// named producer/consumer barriers (384 = full CTA count each phase)
#define BAR_ARV(id)  asm volatile("bar.arrive %0, %1;" :: "r"(id), "r"(384) : "memory")
#define BAR_WAIT(id) asm volatile("bar.sync %0, %1;"   :: "r"(id), "r"(384) : "memory")

// HW tanh (MUFU.TANH): 1 instruction, rel err ~2^-11.
__device__ __forceinline__ float tanh_hw(float x) {
    float r;
    asm("tanh.approx.f32 %0, %1;" : "=f"(r) : "f"(x));
    return r;
}

// packed f32x2 ops (FFMA2/FMUL2 — PTX-only, ptxas never auto-fuses)
__device__ __forceinline__ ull mul2(ull a, ull b) {
    ull r; asm("mul.rn.f32x2 %0, %1, %2;" : "=l"(r) : "l"(a), "l"(b)); return r;
}
__device__ __forceinline__ ull fma2(ull a, ull b, ull c) {
    ull r; asm("fma.rn.f32x2 %0, %1, %2, %3;" : "=l"(r) : "l"(a), "l"(b), "l"(c)); return r;
}
__device__ __forceinline__ void unpack2(ull v, float& lo, float& hi) {
    asm("mov.b64 {%0, %1}, %2;" : "=f"(lo), "=f"(hi) : "l"(v));
}

__constant__ ull HALF_HALF = 0x3F0000003F000000ULL;  // (0.5f, 0.5f)
__constant__ ull ONE_HALF  = 0x3F0000003F800000ULL;  // (1.0f lo, 0.5f hi)

// ---------------------------------------------------------------------------
// Kernel A: xp trig with PAIRED slot order (verbatim R14 — measured fine).
// slot s (0..11): p=s>>1, h=s&1; p<3: W = h?Wi:Wf, wire q=p+1;
//                               p>=3: W = h?Wo:Wu, wire q=p-2.
// Writer stores (cLo,cHi,sLo,sHi) so one LDG.128 yields both packed operands.
// ---------------------------------------------------------------------------
__global__ __launch_bounds__(128, 3) void precompute_kernel(
    const float* __restrict__ x,
    const float* __restrict__ Wf, const float* __restrict__ bf, const float* __restrict__ pf,
    const float* __restrict__ Wi, const float* __restrict__ bi, const float* __restrict__ pi,
    const float* __restrict__ Wu, const float* __restrict__ bu, const float* __restrict__ pu,
    const float* __restrict__ Wo, const float* __restrict__ bo, const float* __restrict__ po)
{
    int tid = threadIdx.x;
    int lane = tid & 31;
    int gwarp = (blockIdx.x * 128 + tid) >> 5;
    int nwarp = (gridDim.x * 128) >> 5;
    const unsigned FULL = 0xffffffffu;

    float4 wa[12], wb[12];
#pragma unroll
    for (int j = 0; j < 12; ++j) {
        int p = j >> 1, h = j & 1;
        const float* Ws = (p < 3) ? (h ? Wi : Wf) : (h ? Wo : Wu);
        int q = (p < 3) ? (p + 1) : (p - 2);
        const float4* r4 = (const float4*)(Ws + q * DH);
        wa[j] = r4[lane];
        wb[j] = r4[32 + lane];
    }

    int b4 = (lane >> 4) & 1, b3 = (lane >> 3) & 1, b2 = (lane >> 2) & 1;
    int myj = (lane & 2) ? (8 + b4 + 2 * b3) : (b4 + 2 * b3 + 4 * b2);
    float off;
    {
        int p = myj >> 1, h = myj & 1;
        const float* bs = (p < 3) ? (h ? bi : bf) : (h ? bo : bu);
        const float* ps = (p < 3) ? (h ? pi : pf) : (h ? po : pu);
        int q = (p < 3) ? (p + 1) : (p - 2);
        off = bs[q] + ps[q];
    }
    bool writer = ((lane & 0x13) == 0) || ((lane & 0x17) == 2);
    int plane = myj >> 1;

    const float4* x4 = (const float4*)x;

    int row = gwarp;
    if (row >= TB) return;
    // software pipeline, prefetch distance 3
    float4 x0a = x4[row * 64 + lane];
    float4 x0b = x4[row * 64 + 32 + lane];
    float4 x1a = make_float4(0.f,0.f,0.f,0.f), x1b = x1a, x2a = x1a, x2b = x1a;
    if (row + nwarp < TB) {
        x1a = x4[(row + nwarp) * 64 + lane];
        x1b = x4[(row + nwarp) * 64 + 32 + lane];
    }
    if (row + 2 * nwarp < TB) {
        x2a = x4[(row + 2 * nwarp) * 64 + lane];
        x2b = x4[(row + 2 * nwarp) * 64 + 32 + lane];
    }

#pragma unroll 3
    for (; row < TB; row += nwarp) {
        int frow = row + 3 * nwarp;
        float4 fa, fb;
        if (frow < TB) {
            fa = x4[frow * 64 + lane];
            fb = x4[frow * 64 + 32 + lane];
        }

        float v[12];
#pragma unroll
        for (int j = 0; j < 12; ++j) {
            v[j] = x0a.x * wa[j].x + x0a.y * wa[j].y + x0a.z * wa[j].z + x0a.w * wa[j].w
                 + x0b.x * wb[j].x + x0b.y * wb[j].y + x0b.z * wb[j].z + x0b.w * wb[j].w;
        }

        // tree-combined multi-reduce: 12 sums in 24 shfls
#pragma unroll
        for (int j = 0; j < 12; ++j)
            v[j] += __shfl_xor_sync(FULL, v[j], 16);
        float w[6];
#pragma unroll
        for (int k = 0; k < 6; ++k) {
            w[k] = (lane & 16) ? v[2 * k + 1] : v[2 * k];
            w[k] += __shfl_xor_sync(FULL, w[k], 8);
        }
        float y[3];
#pragma unroll
        for (int m = 0; m < 3; ++m) {
            y[m] = (lane & 8) ? w[2 * m + 1] : w[2 * m];
            y[m] += __shfl_xor_sync(FULL, y[m], 4);
        }
        float z0 = (lane & 4) ? y[1] : y[0];
        float z1 = y[2];
        z0 += __shfl_xor_sync(FULL, z0, 2);
        z1 += __shfl_xor_sync(FULL, z1, 2);
        float u = (lane & 2) ? z1 : z0;
        u += __shfl_xor_sync(FULL, u, 1);

        float th = u + off;
        float s, c;
        __sincosf(th, &s, &c);
        float c1 = __shfl_xor_sync(FULL, c, 16);
        float s1 = __shfl_xor_sync(FULL, s, 16);
        if (writer) {
            int t = row >> 8, h = row & 255;
            g_trig4[(t * 6 + plane) * 256 + h] = make_float4(c, c1, s, s1);
        }

        x0a = x1a; x0b = x1b;
        x1a = x2a; x1b = x2b;
        x2a = fa;  x2b = fb;
    }
}

// ---------------------------------------------------------------------------
// Kernel B: warp-specialized recurrence, packed gates with ZERO-overhead
// operand loads: one LDG.128 = ulonglong2{(cLo,cHi),(sLo,sHi)} — the packed
// f32x2 operands ARE the load results (no movs, 6 loads/step as in R13).
//   gate warps 0-7  (256 thr): per-h gate math, cv in register
//   reduce warps 8-11: warp rw owns gate rw; stores cos and NEGATED sin into
//     paired layout chs2/shs2.
// ---------------------------------------------------------------------------
__device__ __forceinline__ void gate_half(
    int t, int pf_t, int tid,
    ulonglong2* V,                  // [6]: .x=(cLo,cHi)  .y=(sLo,sHi)
    float& cvr, float* hv_sm, float* chs2, float* shs2)
{
    // packed cs pairs: C[p] = (cos_lo, cos_hi), Sn[p] = (-sin_lo, -sin_hi)
    ulonglong2 Cq0 = *(const ulonglong2*)(chs2 + 0);
    ulonglong2 Cq1 = *(const ulonglong2*)(chs2 + 4);
    ulonglong2 Cq2 = *(const ulonglong2*)(chs2 + 8);
    ulonglong2 Sq0 = *(const ulonglong2*)(shs2 + 0);
    ulonglong2 Sq1 = *(const ulonglong2*)(shs2 + 4);
    ulonglong2 Sq2 = *(const ulonglong2*)(shs2 + 8);

    // r[p] = cos(xp)*C + sin(xp)*(-S), two wires per op
    ull r0 = fma2(V[0].y, Sq0.x, mul2(V[0].x, Cq0.x));
    ull r1 = fma2(V[1].y, Sq0.y, mul2(V[1].x, Cq0.y));
    ull r2 = fma2(V[2].y, Sq1.x, mul2(V[2].x, Cq1.x));
    ull r3 = fma2(V[3].y, Sq1.y, mul2(V[3].x, Cq1.y));
    ull r4 = fma2(V[4].y, Sq2.x, mul2(V[4].x, Cq2.x));
    ull r5 = fma2(V[5].y, Sq2.y, mul2(V[5].x, Cq2.y));

    // products: (f_arg, i_arg) and (g_arg, o_arg)
    ull AB = mul2(mul2(r0, r1), r2);
    ull CD = mul2(mul2(r3, r4), r5);
    AB = mul2(AB, HALF_HALF);   // halve both (sigmoid args)
    CD = mul2(CD, ONE_HALF);    // g unscaled, o halved

    float a, b, c, d;
    unpack2(AB, a, b);
    unpack2(CD, c, d);
    float f  = __fmaf_rn(0.5f, tanh_hw(a), 0.5f);
    float i  = __fmaf_rn(0.5f, tanh_hw(b), 0.5f);
    float g  = tanh_hw(c);
    float o  = __fmaf_rn(0.5f, tanh_hw(d), 0.5f);

    cvr = __fmaf_rn(f, cvr, i * g);
    float hx = o * tanh_hw(cvr);
    hv_sm[tid] = hx;
    BAR_ARV(1);                     // hv ready

    g_hseq[t * 256 + tid] = hx;     // off-chain
    if (pf_t < TT) {                // prefetch distance 2: 6x LDG.128
        const ulonglong2* tp = (const ulonglong2*)g_trig4
                             + (size_t)pf_t * 1536 + tid;
        V[0] = tp[0];    V[1] = tp[256];  V[2] = tp[512];
        V[3] = tp[768];  V[4] = tp[1024]; V[5] = tp[1280];
    }
    BAR_WAIT(2);                    // cs(t) ready for next half-step
}

// pairwise-tree 8-element dot
__device__ __forceinline__ float dot8(float4 wa, float4 wb, float4 ha, float4 hb)
{
    float m0 = __fmaf_rn(wa.y, ha.y, wa.x * ha.x);
    float m1 = __fmaf_rn(wa.w, ha.w, wa.z * ha.z);
    float m2 = __fmaf_rn(wb.y, hb.y, wb.x * hb.x);
    float m3 = __fmaf_rn(wb.w, hb.w, wb.z * hb.z);
    return (m0 + m1) + (m2 + m3);
}

__global__ __launch_bounds__(384, 1) void recurrence_kernel(
    const float* __restrict__ Wf, const float* __restrict__ Wi,
    const float* __restrict__ Wu, const float* __restrict__ Wo)
{
    __shared__ __align__(16) float hv_sm[256];
    __shared__ __align__(16) float chs2[12];   // cos, paired layout
    __shared__ __align__(16) float shs2[12];   // NEGATED sin, paired layout

    int tid = threadIdx.x;
    int lane = tid & 31, warp = tid >> 5;

    if (tid < 12) { chs2[tid] = 1.0f; shs2[tid] = 0.0f; }  // hvec0=0 -> hdot=0
    __syncthreads();

    if (warp < 8) {
        // ---------------- gate role ----------------
        float cvr = 0.0f;
        ulonglong2 A[6], B[6];
        {
            const ulonglong2* tp0 = (const ulonglong2*)g_trig4 + tid;
            const ulonglong2* tp1 = (const ulonglong2*)g_trig4 + 1536 + tid;
#pragma unroll
            for (int p = 0; p < 6; ++p) {
                A[p] = tp0[256 * p];
                B[p] = tp1[256 * p];
            }
        }
        for (int t = 0; t < TT; t += 2) {
            gate_half(t,     t + 2, tid, A, cvr, hv_sm, chs2, shs2);
            gate_half(t + 1, t + 3, tid, B, cvr, hv_sm, chs2, shs2);
        }
        g_cvec[tid] = cvr;
    } else {
        // ---------------- reduce role ----------------
        int rw = warp - 8;   // 0..3 -> f, i, g(u), o ; wires 1-3
        const float* Wsel = (rw == 0) ? Wf : (rw == 1) ? Wi : (rw == 2) ? Wu : Wo;
        float4 wa[3], wb[3];
#pragma unroll
        for (int k = 0; k < 3; ++k) {
            const float4* Wr4 = (const float4*)(Wsel + (1 + k) * DH + DD);
            wa[k] = Wr4[lane];
            wb[k] = Wr4[32 + lane];
        }
        const float4* hv4 = (const float4*)hv_sm;
        // lanes 0..5: kk = wire-1 = lane>>1; odd lane = (negated) sin
        int kk = lane >> 1;
        float* dst = (lane & 1) ? shs2 : chs2;
        // paired layout index: plane p = kk + 3*(rw>>1), half = rw&1
        int jj = 2 * (kk + 3 * (rw >> 1)) + (rw & 1);

        for (int t = 0; t < TT; ++t) {
            BAR_WAIT(1);            // hv ready
            float4 ha = hv4[lane];
            float4 hb = hv4[32 + lane];
            float s0 = dot8(wa[0], wb[0], ha, hb);
            float s1 = dot8(wa[1], wb[1], ha, hb);
            float s2 = dot8(wa[2], wb[2], ha, hb);
#pragma unroll
            for (int off = 16; off > 0; off >>= 1) {
                s0 += __shfl_xor_sync(0xffffffffu, s0, off);
                s1 += __shfl_xor_sync(0xffffffffu, s1, off);
                s2 += __shfl_xor_sync(0xffffffffu, s2, off);
            }
            if (lane < 6) {
                float sv = (kk == 0) ? s0 : (kk == 1) ? s1 : s2;
                float r = (lane & 1) ? -__sinf(sv) : __cosf(sv);
                dst[jj] = r;
            }
            BAR_ARV(2);             // cs ready
        }
    }
}

// ---------------------------------------------------------------------------
// Kernel C: broadcast outputs. out = [outs (T,B,H) | hx (B,H) | cx (B,H)],
// every b-row identical. Pure write bandwidth, float4.
// ---------------------------------------------------------------------------
__global__ void writeout_kernel(float4* __restrict__ out4)
{
    const int OUTS4 = TT * BB * (HH / 4);   // 8388608
    const int BH4 = BB * (HH / 4);          // 16384
    int i4 = blockIdx.x * blockDim.x + threadIdx.x;
    const float4* hs4 = (const float4*)g_hseq;
    const float4* cv4 = (const float4*)g_cvec;
    if (i4 < OUTS4) {
        int t = i4 >> 14;          // / (B*H/4)
        int h4 = i4 & 63;
        out4[i4] = hs4[t * 64 + h4];
    } else if (i4 < OUTS4 + BH4) {
        int h4 = i4 & 63;
        out4[i4] = hs4[(TT - 1) * 64 + h4];
    } else if (i4 < OUTS4 + 2 * BH4) {
        int h4 = i4 & 63;
        out4[i4] = cv4[h4];
    }
}

extern "C" void kernel_launch(void* const* d_in, const int* in_sizes, int n_in,
                              void* d_out, int out_size)
{
    const float* x  = (const float*)d_in[0];
    const float* Wf = (const float*)d_in[1];
    const float* bf = (const float*)d_in[2];
    const float* pf = (const float*)d_in[3];
    const float* Wi = (const float*)d_in[4];
    const float* bi = (const float*)d_in[5];
    const float* pi = (const float*)d_in[6];
    const float* Wu = (const float*)d_in[7];
    const float* bu = (const float*)d_in[8];
    const float* pu = (const float*)d_in[9];
    const float* Wo = (const float*)d_in[10];
    const float* bo = (const float*)d_in[11];
    const float* po = (const float*)d_in[12];

    precompute_kernel<<<444, 128>>>(x, Wf, bf, pf, Wi, bi, pi,
                                       Wu, bu, pu, Wo, bo, po);
    recurrence_kernel<<<1, 384>>>(Wf, Wi, Wu, Wo);

    const int total4 = (TT * BB * HH + 2 * BB * HH) / 4;   // 8421376
    writeout_kernel<<<(total4 + 255) / 256, 256>>>((float4*)d_out);
}